// round 12
// baseline (speedup 1.0000x reference)
#include <cuda_runtime.h>

// db4 wavedec level-4 (mode='symmetric'), one CTA per (b,c) row.
// R11: batched register preloads. Each thread's chunk of outputs preloads all
// needed polyphase pairs into registers (12 consecutive LDS.64 -> MLP ~12, one
// scoreboard wait) before a pure FFMA2 chunk. __launch_bounds__(NT,3) lets
// ptxas use the ~85 regs/thread that the smem-capped occupancy makes free.
//
// Output row layout (8218 f32): [cA4:518 | cD4:518 | cD3:1030 | cD2:2053 | cD1:4099]

#define L0    8192
#define O1    4099
#define O2    2053
#define O3    1030
#define O4    518
#define TOT   8218

#define NROWS 2048
#define NT    256

// SMEM layout (floats). Each buffer: [8-word left ext | body | right ext/pad].
#define CAP_A 8248          // worst level-1 tail read: float idx 8235 < 8248
#define CAP_B 4152          // worst level-2 tail read: float idx 4129 < 4152
#define CAP_S 4100          // cD scratch (max O1)
#define SMEM_FLOATS (CAP_A + CAP_B + CAP_S)   // 16500
#define SMEM_BYTES  (SMEM_FLOATS * 4)         // 66000

// pywt db4 rec_lo
#define R0  0.23037781330885523f
#define R1  0.7148465705525415f
#define R2  0.6308807679295904f
#define R3 (-0.02798376941698385f)
#define R4 (-0.18703481171888114f)
#define R5  0.030841381835986965f
#define R6  0.032883011666982945f
#define R7 (-0.010597401784997278f)

typedef unsigned long long u64;

static __device__ __forceinline__ u64 pack2(float lo, float hi) {
    u64 r;
    asm("mov.b64 %0, {%1, %2};" : "=l"(r) : "f"(lo), "f"(hi));
    return r;
}
static __device__ __forceinline__ u64 mul2(u64 a, u64 b) {
    u64 d;
    asm("mul.rn.f32x2 %0, %1, %2;" : "=l"(d) : "l"(a), "l"(b));
    return d;
}
static __device__ __forceinline__ u64 fma2(u64 a, u64 b, u64 c) {
    u64 d;
    asm("fma.rn.f32x2 %0, %1, %2, %3;" : "=l"(d) : "l"(a), "l"(b), "l"(c));
    return d;
}
static __device__ __forceinline__ float hadd2(u64 v) {
    float x, y;
    asm("mov.b64 {%0, %1}, %2;" : "=f"(x), "=f"(y) : "l"(v));
    return x + y;
}

// Packed polyphase coefficients.
struct Coef {
    u64 cl0, cl1, cl2, cl3;   // lo filter: (R0,R1)(R2,R3)(R4,R5)(R6,R7)
    u64 ch0, ch1, ch2, ch3;   // hi filter: H_t = (-1)^t R_{7-t}
};
static __device__ __forceinline__ Coef make_coef() {
    Coef c;
    c.cl0 = pack2(R0, R1);  c.cl1 = pack2(R2, R3);
    c.cl2 = pack2(R4, R5);  c.cl3 = pack2(R6, R7);
    c.ch0 = pack2(R7, -R6); c.ch1 = pack2(R5, -R4);
    c.ch2 = pack2(R3, -R2); c.ch3 = pack2(R1, -R0);
    return c;
}

// Fill symmetric extension of a buffer whose body (length n) sits at b+8.
static __device__ __forceinline__ void fill_ext(float* b, int n) {
    int t = threadIdx.x;
    if (t < 6) {
        b[2 + t] = b[8 + 5 - t];
    } else if (t < 13) {
        int m = t - 6;
        b[8 + n + m] = b[8 + n - 1 - m];
    }
}

// One DWT level. p_k = (ext[2k], ext[2k+1]); output i uses p_{i+1}..p_{i+4}.
// Thread t owns outputs [t*T, t*T+T), processed in chunks of <=CH outputs:
// preload CH+3 pairs into registers (batched LDS.64), then pure FFMA2.
#define CH 9
template<int T>
static __device__ __forceinline__ void dwt_level_reg(
    const float* __restrict__ ext, int n_out,
    float* __restrict__ outA, float* __restrict__ outD)
{
    const int i0 = threadIdx.x * T;
    if (i0 >= n_out) return;

    const Coef c = make_coef();
    const u64* pp = reinterpret_cast<const u64*>(ext) + (i0 + 1);
    const bool full = (i0 + T <= n_out);

    #pragma unroll
    for (int base = 0; base < T; base += CH) {
        constexpr int B0 = 0;  (void)B0;
        const int Bn = (T - base < CH) ? (T - base) : CH;   // compile-time per unroll

        u64 p[CH + 3];
        #pragma unroll
        for (int k = 0; k < CH + 3; k++)
            if (k < Bn + 3) p[k] = pp[base + k];

        if (full) {
            #pragma unroll
            for (int j = 0; j < CH; j++) {
                if (j < Bn) {
                    u64 al = mul2(c.cl0, p[j]);
                    al = fma2(c.cl1, p[j + 1], al);
                    al = fma2(c.cl2, p[j + 2], al);
                    al = fma2(c.cl3, p[j + 3], al);
                    u64 ah = mul2(c.ch0, p[j]);
                    ah = fma2(c.ch1, p[j + 1], ah);
                    ah = fma2(c.ch2, p[j + 2], ah);
                    ah = fma2(c.ch3, p[j + 3], ah);
                    outA[i0 + base + j] = hadd2(al);
                    outD[i0 + base + j] = hadd2(ah);
                }
            }
        } else {
            #pragma unroll
            for (int j = 0; j < CH; j++) {
                if (j < Bn && i0 + base + j < n_out) {
                    u64 al = mul2(c.cl0, p[j]);
                    al = fma2(c.cl1, p[j + 1], al);
                    al = fma2(c.cl2, p[j + 2], al);
                    al = fma2(c.cl3, p[j + 3], al);
                    u64 ah = mul2(c.ch0, p[j]);
                    ah = fma2(c.ch1, p[j + 1], ah);
                    ah = fma2(c.ch2, p[j + 2], ah);
                    ah = fma2(c.ch3, p[j + 3], ah);
                    outA[i0 + base + j] = hadd2(al);
                    outD[i0 + base + j] = hadd2(ah);
                }
            }
        }
    }
}

__global__ void __launch_bounds__(NT, 3)
wavedec_db4_l4_kernel(const float* __restrict__ x, float* __restrict__ out)
{
    extern __shared__ float sm[];
    float* A = sm;                   // ext buffer A, body at A+8
    float* B = sm + CAP_A;           // ext buffer B, body at B+8 (8B-aligned)
    float* S = sm + CAP_A + CAP_B;   // cD staging scratch

    const int row = blockIdx.x;
    const float* xr = x + (size_t)row * L0;
    float* orow = out + (size_t)row * TOT;

    // Load row into A body (32B-aligned float4)
    {
        const float4* x4 = reinterpret_cast<const float4*>(xr);
        float4* a4 = reinterpret_cast<float4*>(A + 8);
        #pragma unroll 4
        for (int i = threadIdx.x; i < L0 / 4; i += NT) a4[i] = x4[i];
    }
    __syncthreads();
    fill_ext(A, L0);
    __syncthreads();

    // Level 1: 8192 -> 4099.  ceil(4099/17)=242 chunks.
    dwt_level_reg<17>(A, O1, B + 8, S);
    __syncthreads();
    fill_ext(B, O1);
    for (int i = threadIdx.x; i < O1; i += NT)
        orow[O4 + O4 + O3 + O2 + i] = S[i];          // cD1
    __syncthreads();

    // Level 2: 4099 -> 2053.  ceil(2053/9)=229 chunks.
    dwt_level_reg<9>(B, O2, A + 8, S);
    __syncthreads();
    fill_ext(A, O2);
    for (int i = threadIdx.x; i < O2; i += NT)
        orow[O4 + O4 + O3 + i] = S[i];               // cD2
    __syncthreads();

    // Level 3: 2053 -> 1030.  ceil(1030/5)=206 chunks.
    dwt_level_reg<5>(A, O3, B + 8, S);
    __syncthreads();
    fill_ext(B, O3);
    for (int i = threadIdx.x; i < O3; i += NT)
        orow[O4 + O4 + i] = S[i];                    // cD3
    __syncthreads();

    // Level 4: 1030 -> 518. Outputs straight to GMEM (tiny, scatter OK).
    dwt_level_reg<3>(B, O4, orow, orow + O4);        // cA4, cD4
}

extern "C" void kernel_launch(void* const* d_in, const int* in_sizes, int n_in,
                              void* d_out, int out_size)
{
    (void)in_sizes; (void)n_in; (void)out_size;
    const float* x = (const float*)d_in[0];
    float* out = (float*)d_out;

    cudaFuncSetAttribute(wavedec_db4_l4_kernel,
                         cudaFuncAttributeMaxDynamicSharedMemorySize, SMEM_BYTES);
    wavedec_db4_l4_kernel<<<NROWS, NT, SMEM_BYTES>>>(x, out);
}

// round 14
// speedup vs baseline: 1.1577x; 1.1577x over previous
#include <cuda_runtime.h>

// db4 wavedec level-4 (mode='symmetric').
// R13: persistent CTAs (grid=444 = 3/SM x 148), each looping rows stride-444,
// with cp.async prefetch of the next row into buffer A while levels 2-4 of the
// current row run. Buffer plan: A(row) -> L1 -> B(cA1) -> L2 -> C(cA2) -> L3
// -> B(cA3) -> L4 -> GMEM; S stages cD for coalesced stores. A is dead after
// L1, so the prefetch overlaps ~4 phases of compute.
//
// Output row layout (8218 f32): [cA4:518 | cD4:518 | cD3:1030 | cD2:2053 | cD1:4099]

#define L0    8192
#define O1    4099
#define O2    2053
#define O3    1030
#define O4    518
#define TOT   8218

#define NROWS 2048
#define NT    256
#define GRID  444     // 148 SMs x 3 CTAs

// SMEM buffers (floats): [8-word left ext | body | right ext/pad]
#define CAP_A 8248    // row; worst L1 tail read float idx 8235
#define CAP_B 4152    // cA1 (worst L2 tail read 4129); later cA3 (L4 reads <1046)
#define CAP_C 2080    // cA2; worst L3 tail read 2067
#define CAP_S 4100    // cD staging (max O1)
#define SMEM_FLOATS (CAP_A + CAP_B + CAP_C + CAP_S)   // 18580
#define SMEM_BYTES  (SMEM_FLOATS * 4)                 // 74320 -> 3 CTAs/SM

// pywt db4 rec_lo
#define R0  0.23037781330885523f
#define R1  0.7148465705525415f
#define R2  0.6308807679295904f
#define R3 (-0.02798376941698385f)
#define R4 (-0.18703481171888114f)
#define R5  0.030841381835986965f
#define R6  0.032883011666982945f
#define R7 (-0.010597401784997278f)

typedef unsigned long long u64;

static __device__ __forceinline__ u64 pack2(float lo, float hi) {
    u64 r; asm("mov.b64 %0, {%1, %2};" : "=l"(r) : "f"(lo), "f"(hi)); return r;
}
static __device__ __forceinline__ u64 mul2(u64 a, u64 b) {
    u64 d; asm("mul.rn.f32x2 %0, %1, %2;" : "=l"(d) : "l"(a), "l"(b)); return d;
}
static __device__ __forceinline__ u64 fma2(u64 a, u64 b, u64 c) {
    u64 d; asm("fma.rn.f32x2 %0, %1, %2, %3;" : "=l"(d) : "l"(a), "l"(b), "l"(c)); return d;
}
static __device__ __forceinline__ float hadd2(u64 v) {
    float x, y; asm("mov.b64 {%0, %1}, %2;" : "=f"(x), "=f"(y) : "l"(v)); return x + y;
}

static __device__ __forceinline__ void cp16(float* smem_dst, const float* gmem_src) {
    unsigned s = (unsigned)__cvta_generic_to_shared(smem_dst);
    asm volatile("cp.async.cg.shared.global [%0], [%1], 16;" :: "r"(s), "l"(gmem_src));
}
static __device__ __forceinline__ void cp_commit() {
    asm volatile("cp.async.commit_group;");
}
static __device__ __forceinline__ void cp_wait0() {
    asm volatile("cp.async.wait_group 0;");
}

struct Coef {
    u64 cl0, cl1, cl2, cl3;   // lo: (R0,R1)(R2,R3)(R4,R5)(R6,R7)
    u64 ch0, ch1, ch2, ch3;   // hi: H_t = (-1)^t R_{7-t}
};
static __device__ __forceinline__ Coef make_coef() {
    Coef c;
    c.cl0 = pack2(R0, R1);  c.cl1 = pack2(R2, R3);
    c.cl2 = pack2(R4, R5);  c.cl3 = pack2(R6, R7);
    c.ch0 = pack2(R7, -R6); c.ch1 = pack2(R5, -R4);
    c.ch2 = pack2(R3, -R2); c.ch3 = pack2(R1, -R0);
    return c;
}

// Symmetric extension for body (length n) at b+8.
static __device__ __forceinline__ void fill_ext(float* b, int n) {
    int t = threadIdx.x;
    if (t < 6) {
        b[2 + t] = b[8 + 5 - t];
    } else if (t < 13) {
        int m = t - 6;
        b[8 + n + m] = b[8 + n - 1 - m];
    }
}

// One DWT level. p_k = (ext[2k], ext[2k+1]); output i uses p_{i+1}..p_{i+4}.
// Thread t owns outputs [t*T, t*T+T), chunks of <=CH with batched preloads.
#define CH 9
template<int T>
static __device__ __forceinline__ void dwt_level_reg(
    const float* __restrict__ ext, int n_out,
    float* __restrict__ outA, float* __restrict__ outD)
{
    const int i0 = threadIdx.x * T;
    if (i0 >= n_out) return;

    const Coef c = make_coef();
    const u64* pp = reinterpret_cast<const u64*>(ext) + (i0 + 1);
    const bool full = (i0 + T <= n_out);

    #pragma unroll
    for (int base = 0; base < T; base += CH) {
        const int Bn = (T - base < CH) ? (T - base) : CH;

        u64 p[CH + 3];
        #pragma unroll
        for (int k = 0; k < CH + 3; k++)
            if (k < Bn + 3) p[k] = pp[base + k];

        #pragma unroll
        for (int j = 0; j < CH; j++) {
            if (j < Bn) {
                u64 al = mul2(c.cl0, p[j]);
                al = fma2(c.cl1, p[j + 1], al);
                al = fma2(c.cl2, p[j + 2], al);
                al = fma2(c.cl3, p[j + 3], al);
                u64 ah = mul2(c.ch0, p[j]);
                ah = fma2(c.ch1, p[j + 1], ah);
                ah = fma2(c.ch2, p[j + 2], ah);
                ah = fma2(c.ch3, p[j + 3], ah);
                if (full || i0 + base + j < n_out) {
                    outA[i0 + base + j] = hadd2(al);
                    outD[i0 + base + j] = hadd2(ah);
                }
            }
        }
    }
}

// Issue cp.async for a full row into A body (8 x 16B per thread).
static __device__ __forceinline__ void prefetch_row(float* Abody, const float* xr) {
    #pragma unroll
    for (int k = 0; k < L0 / 4 / NT; k++) {
        int i = threadIdx.x + k * NT;
        cp16(Abody + 4 * i, xr + 4 * i);
    }
    cp_commit();
}

__global__ void __launch_bounds__(NT, 3)
wavedec_db4_l4_kernel(const float* __restrict__ x, float* __restrict__ out)
{
    extern __shared__ float sm[];
    float* A = sm;                          // row buffer
    float* B = sm + CAP_A;                  // cA1, later cA3
    float* C = sm + CAP_A + CAP_B;          // cA2
    float* S = sm + CAP_A + CAP_B + CAP_C;  // cD staging

    // Prologue: prefetch first row
    {
        const float* xr0 = x + (size_t)blockIdx.x * L0;
        prefetch_row(A + 8, xr0);
    }

    for (int r = blockIdx.x; r < NROWS; r += GRID) {
        float* orow = out + (size_t)r * TOT;

        cp_wait0();
        __syncthreads();                    // A row resident
        fill_ext(A, L0);
        __syncthreads();

        // Level 1: 8192 -> 4099 (cA1 -> B, cD1 -> S). ceil(4099/17)=242.
        dwt_level_reg<17>(A, O1, B + 8, S);
        __syncthreads();                    // A dead from here

        // Prefetch next row into A (overlaps L2..L4)
        {
            int rn = r + GRID;
            if (rn < NROWS) prefetch_row(A + 8, x + (size_t)rn * L0);
        }
        fill_ext(B, O1);
        for (int i = threadIdx.x; i < O1; i += NT)
            orow[O4 + O4 + O3 + O2 + i] = S[i];          // cD1
        __syncthreads();

        // Level 2: 4099 -> 2053 (cA2 -> C, cD2 -> S). ceil(2053/9)=229.
        dwt_level_reg<9>(B, O2, C + 8, S);
        __syncthreads();
        fill_ext(C, O2);
        for (int i = threadIdx.x; i < O2; i += NT)
            orow[O4 + O4 + O3 + i] = S[i];               // cD2
        __syncthreads();

        // Level 3: 2053 -> 1030 (cA3 -> B, cD3 -> S). ceil(1030/5)=206.
        dwt_level_reg<5>(C, O3, B + 8, S);
        __syncthreads();
        fill_ext(B, O3);
        for (int i = threadIdx.x; i < O3; i += NT)
            orow[O4 + O4 + i] = S[i];                    // cD3
        __syncthreads();

        // Level 4: 1030 -> 518, straight to GMEM.
        dwt_level_reg<3>(B, O4, orow, orow + O4);        // cA4, cD4
        __syncthreads();                    // B/C/S reusable next iteration
    }
}

extern "C" void kernel_launch(void* const* d_in, const int* in_sizes, int n_in,
                              void* d_out, int out_size)
{
    (void)in_sizes; (void)n_in; (void)out_size;
    const float* x = (const float*)d_in[0];
    float* out = (float*)d_out;

    cudaFuncSetAttribute(wavedec_db4_l4_kernel,
                         cudaFuncAttributeMaxDynamicSharedMemorySize, SMEM_BYTES);
    wavedec_db4_l4_kernel<<<GRID, NT, SMEM_BYTES>>>(x, out);
}